// round 14
// baseline (speedup 1.0000x reference)
#include <cuda_runtime.h>
#include <cstdint>

// ============================================================================
// AttentionBlock via mma.sync tf32 (baseline PTX target sm_103).
//   GroupNorm -> hnT (tf32, transposed)
//   qT = hnT·Wq^T, kT = hnT·Wk^T ; v = Wv·hnT^T   (tf32 out)
//   S = scale·(qT·kT^T) -> row softmax (tf32 out) -> haT = P·v^T
//   out = x + Wp·haT^T + bp
//
// R14: GEMM reworked for tensor-pipe utilization:
//   128-thread CTA (4 warps, 2x2), warp tile 64x64 (4x8 m16n8k8 frags),
//   launch_bounds(128,2) -> 256 regs/thread budget at 2 CTA/SM,
//   double-buffered fragments (LDS for ks+1 overlaps MMA of ks),
//   LDS:MMA = 1.0 (was 1.5), 3-stage cp.async pipeline.
// Statics: all symbols <= 64 MB (container constraint).
// ============================================================================

namespace cfg {
constexpr int BATCH = 8;
constexpr int C     = 512;
constexpr int HW    = 4096;
constexpr int NG    = 32;
constexpr int CPG   = C / NG;
constexpr float EPS   = 1e-5f;
constexpr float SCALE = 0.04419417382415922f;  // 1/sqrt(512)

constexpr size_t SZ_CH = (size_t)BATCH * C * HW;   // 64 MB
constexpr size_t SZ_S1 = (size_t)HW * HW;          // 64 MB (one batch)
}

__device__ float g_hnT[cfg::SZ_CH];
__device__ float g_qT [cfg::SZ_CH];
__device__ float g_kT [cfg::SZ_CH];
__device__ float g_v  [cfg::SZ_CH];
__device__ float g_S0 [cfg::SZ_S1];
__device__ float g_S1 [cfg::SZ_S1];
__device__ float g_W  [4][cfg::C * cfg::C];

// -------------------- helpers ------------------------------------------------
__device__ __forceinline__ float tf32r(float x) {
    uint32_t u;
    asm("cvt.rna.tf32.f32 %0, %1;" : "=r"(u) : "f"(x));
    return __uint_as_float(u);
}
__device__ __forceinline__ uint32_t smem_u32(const void* p) {
    uint32_t a;
    asm("{ .reg .u64 t; cvta.to.shared.u64 t, %1; cvt.u32.u64 %0, t; }"
        : "=r"(a) : "l"(p));
    return a;
}
__device__ __forceinline__ void cp16(uint32_t dst, const void* src) {
    asm volatile("cp.async.cg.shared.global [%0], [%1], 16;"
                 :: "r"(dst), "l"(src));
}
__device__ __forceinline__ void cp_commit() {
    asm volatile("cp.async.commit_group;" ::: "memory");
}
template<int N> __device__ __forceinline__ void cp_wait() {
    asm volatile("cp.async.wait_group %0;" :: "n"(N) : "memory");
}
__device__ __forceinline__ void mma_tf32(float* d, const uint32_t* a,
                                         const uint32_t* b) {
    asm volatile(
        "mma.sync.aligned.m16n8k8.row.col.f32.tf32.tf32.f32 "
        "{%0,%1,%2,%3}, {%4,%5,%6,%7}, {%8,%9}, {%0,%1,%2,%3};"
        : "+f"(d[0]), "+f"(d[1]), "+f"(d[2]), "+f"(d[3])
        : "r"(a[0]), "r"(a[1]), "r"(a[2]), "r"(a[3]), "r"(b[0]), "r"(b[1]));
}

// -------------------- GroupNorm -> transposed tf32 output -------------------
__global__ __launch_bounds__(512)
void groupnorm_t_kernel(const float* __restrict__ x,
                        const float* __restrict__ gamma,
                        const float* __restrict__ beta,
                        float* __restrict__ outT)
{
    using namespace cfg;
    __shared__ float shs[16], shss[16];
    const int b = blockIdx.x >> 5;
    const int g = blockIdx.x & 31;
    const size_t base = ((size_t)b * C + (size_t)g * CPG) * HW;
    const int n = CPG * HW;

    float s = 0.f, ss = 0.f;
    for (int i = threadIdx.x; i < n; i += 512) {
        float v = x[base + i];
        s += v; ss += v * v;
    }
#pragma unroll
    for (int o = 16; o; o >>= 1) {
        s  += __shfl_xor_sync(0xffffffffu, s,  o);
        ss += __shfl_xor_sync(0xffffffffu, ss, o);
    }
    const int w = threadIdx.x >> 5;
    if ((threadIdx.x & 31) == 0) { shs[w] = s; shss[w] = ss; }
    __syncthreads();
    s = 0.f; ss = 0.f;
#pragma unroll
    for (int i = 0; i < 16; i++) { s += shs[i]; ss += shss[i]; }

    const float mean = s / n;
    const float var  = ss / n - mean * mean;
    const float rstd = rsqrtf(var + EPS);

    float gm[16], bt[16];
#pragma unroll
    for (int c = 0; c < 16; c++) {
        gm[c] = gamma[g * CPG + c] * rstd;
        bt[c] = beta[g * CPG + c];
    }
    for (int hw = threadIdx.x; hw < HW; hw += 512) {
        float vals[16];
#pragma unroll
        for (int c = 0; c < 16; c++)
            vals[c] = tf32r((x[base + (size_t)c * HW + hw] - mean) * gm[c] + bt[c]);
        float4* dst = reinterpret_cast<float4*>(
            outT + ((size_t)b * HW + hw) * C + g * CPG);
#pragma unroll
        for (int j = 0; j < 4; j++)
            dst[j] = make_float4(vals[4*j], vals[4*j+1], vals[4*j+2], vals[4*j+3]);
    }
}

// -------------------- round all 4 weights in one launch ----------------------
__global__ __launch_bounds__(256)
void round4_kernel(const float* __restrict__ w0, const float* __restrict__ w1,
                   const float* __restrict__ w2, const float* __restrict__ w3,
                   float* __restrict__ out, int n)
{
    int i = blockIdx.x * 256 + threadIdx.x;
    if (i < n) {
        out[i]         = tf32r(w0[i]);
        out[i + n]     = tf32r(w1[i]);
        out[i + 2 * n] = tf32r(w2[i]);
        out[i + 3 * n] = tf32r(w3[i]);
    }
}

// -------------------- Row softmax over 4096 (tf32 out), two buffers ---------
__global__ __launch_bounds__(256)
void softmax_kernel(float* __restrict__ S0, float* __restrict__ S1)
{
    using namespace cfg;
    __shared__ float shm[8], shsum[8];
    const int row = blockIdx.x;
    float* p = (row < HW) ? (S0 + (size_t)row * HW)
                          : (S1 + (size_t)(row - HW) * HW);
    const int t = threadIdx.x;

    float vals[16];
    float m = -3.4e38f;
#pragma unroll
    for (int i = 0; i < 16; i++) {
        vals[i] = p[t + i * 256];
        m = fmaxf(m, vals[i]);
    }
#pragma unroll
    for (int o = 16; o; o >>= 1) m = fmaxf(m, __shfl_xor_sync(0xffffffffu, m, o));
    if ((t & 31) == 0) shm[t >> 5] = m;
    __syncthreads();
    m = shm[0];
#pragma unroll
    for (int w = 1; w < 8; w++) m = fmaxf(m, shm[w]);

    float s = 0.f;
#pragma unroll
    for (int i = 0; i < 16; i++) {
        vals[i] = __expf(vals[i] - m);
        s += vals[i];
    }
#pragma unroll
    for (int o = 16; o; o >>= 1) s += __shfl_xor_sync(0xffffffffu, s, o);
    if ((t & 31) == 0) shsum[t >> 5] = s;
    __syncthreads();
    s = 0.f;
#pragma unroll
    for (int w = 0; w < 8; w++) s += shsum[w];

    const float inv = 1.f / s;
#pragma unroll
    for (int i = 0; i < 16; i++) p[t + i * 256] = tf32r(vals[i] * inv);
}

// ============================================================================
// GEMM: 128x128x32 tile, 128 threads (4 warps 2x2), warp tile 64x64,
// double-buffered fragments, 3-stage cp.async, 2 CTAs/SM (256 reg budget).
//   D = scale*A·B^T (+bias[m]/[n]) (+resid); Aalt/Dalt replace A/D at z==1.
// ============================================================================
namespace mg {
constexpr int BM = 128, BN = 128, BK = 32;
constexpr int STAGE_BYTES = (BM + BN) * BK * 4;      // 32 KB
constexpr int NSTAGE = 3;
constexpr int SMEM_BYTES = NSTAGE * STAGE_BYTES;     // 96 KB
constexpr int NTHR = 128;
}

__global__ __launch_bounds__(128, 2)
void mma_gemm(const float* __restrict__ A, const float* __restrict__ Aalt,
              const float* __restrict__ B,
              float* __restrict__ D, float* __restrict__ Dalt,
              int M, int N, int K,
              size_t sA, size_t sB, size_t sD,
              const float* __restrict__ bias, int bias_mode,
              const float* __restrict__ resid, size_t sR,
              float scale, int round_out)
{
    using namespace mg;
    extern __shared__ char smem[];
    const uint32_t sbase = smem_u32(smem);

    const int z = blockIdx.z;
    if (Aalt && z == 1) A = Aalt; else A += (size_t)z * sA;
    B += (size_t)z * sB;
    if (Dalt && z == 1) D = Dalt; else D += (size_t)z * sD;

    const int bm = blockIdx.y * BM;
    const int bn = blockIdx.x * BN;
    const int tid = threadIdx.x;
    const int wid = tid >> 5, lid = tid & 31;
    const int wm = wid >> 1;           // 0..1 (64 rows)
    const int wn = wid & 1;            // 0..1 (64 cols)
    const int grp = lid >> 2, thr = lid & 3;
    const int NC = K / BK;

    // ---- load geometry: 8 16B-chunks per tile per thread ----
    uint32_t dstA[8], dstB[8];
    const float* srcA[8];
    const float* srcB[8];
#pragma unroll
    for (int l = 0; l < 8; l++) {
        const int c = tid + l * NTHR;      // 0..1023
        const int row = c >> 3, u = c & 7;
        const uint32_t sw = row * 128 + ((u * 16) ^ ((row & 7) << 4));
        dstA[l] = sbase + sw;
        dstB[l] = sbase + BM * BK * 4 + sw;
        srcA[l] = A + (size_t)(bm + row) * K + u * 4;
        srcB[l] = B + (size_t)(bn + row) * K + u * 4;
    }

    auto load_chunk = [&](int kc) {
        const uint32_t so = (kc % NSTAGE) * STAGE_BYTES;
        const int ko = kc * BK;
#pragma unroll
        for (int l = 0; l < 8; l++) cp16(dstA[l] + so, srcA[l] + ko);
#pragma unroll
        for (int l = 0; l < 8; l++) cp16(dstB[l] + so, srcB[l] + ko);
        cp_commit();
    };

    float acc[4][8][4];
#pragma unroll
    for (int i = 0; i < 4; i++)
#pragma unroll
        for (int j = 0; j < 8; j++)
#pragma unroll
            for (int r = 0; r < 4; r++) acc[i][j][r] = 0.f;

    load_chunk(0);
    load_chunk(1);

    const uint32_t xorv = (uint32_t)(grp << 4);

    uint32_t afr[2][4][4];   // [buf][mt][frag]
    uint32_t bfr[2][8][2];   // [buf][nt][frag]

    auto load_frags = [&](const char* Abase, const char* Bbase, int ks, int buf) {
        const uint32_t c0 = (uint32_t)((ks * 8 + thr) * 4) ^ xorv;
        const uint32_t c1 = (uint32_t)((ks * 8 + thr + 4) * 4) ^ xorv;
#pragma unroll
        for (int mt = 0; mt < 4; mt++) {
            const int r0 = wm * 64 + mt * 16 + grp;
            afr[buf][mt][0] = *(const uint32_t*)(Abase + r0 * 128 + c0);
            afr[buf][mt][1] = *(const uint32_t*)(Abase + (r0 + 8) * 128 + c0);
            afr[buf][mt][2] = *(const uint32_t*)(Abase + r0 * 128 + c1);
            afr[buf][mt][3] = *(const uint32_t*)(Abase + (r0 + 8) * 128 + c1);
        }
#pragma unroll
        for (int nt = 0; nt < 8; nt++) {
            const int rB = wn * 64 + nt * 8 + grp;
            bfr[buf][nt][0] = *(const uint32_t*)(Bbase + rB * 128 + c0);
            bfr[buf][nt][1] = *(const uint32_t*)(Bbase + rB * 128 + c1);
        }
    };

    for (int kc = 0; kc < NC; kc++) {
        if (kc < NC - 1) cp_wait<1>(); else cp_wait<0>();
        __syncthreads();
        if (kc + 2 < NC) load_chunk(kc + 2);

        const char* Abase = smem + (kc % NSTAGE) * STAGE_BYTES;
        const char* Bbase = Abase + BM * BK * 4;

        load_frags(Abase, Bbase, 0, 0);
#pragma unroll
        for (int ks = 0; ks < BK / 8; ks++) {
            const int cur = ks & 1;
            if (ks < BK / 8 - 1) load_frags(Abase, Bbase, ks + 1, cur ^ 1);
#pragma unroll
            for (int mt = 0; mt < 4; mt++)
#pragma unroll
                for (int nt = 0; nt < 8; nt++)
                    mma_tf32(acc[mt][nt], afr[cur][mt], bfr[cur][nt]);
        }
    }

    // ---- epilogue ----
#pragma unroll
    for (int mt = 0; mt < 4; mt++) {
#pragma unroll
        for (int half = 0; half < 2; half++) {
            const int m = bm + wm * 64 + mt * 16 + grp + half * 8;
            const float biasM = (bias_mode == 1) ? bias[m] : 0.f;
#pragma unroll
            for (int nt = 0; nt < 8; nt++) {
                const int n = bn + wn * 64 + nt * 8 + 2 * thr;
                float v0 = acc[mt][nt][half * 2 + 0] * scale;
                float v1 = acc[mt][nt][half * 2 + 1] * scale;
                if (bias_mode == 1) { v0 += biasM; v1 += biasM; }
                else if (bias_mode == 2) { v0 += bias[n]; v1 += bias[n + 1]; }
                const size_t off = (size_t)m * N + n;
                if (resid) {
                    const float* rp = resid + (size_t)z * sR;
                    v0 += rp[off]; v1 += rp[off + 1];
                }
                if (round_out) { v0 = tf32r(v0); v1 = tf32r(v1); }
                *reinterpret_cast<float2*>(D + off) = make_float2(v0, v1);
            }
        }
    }
}

// -------------------- launch ------------------------------------------------
extern "C" void kernel_launch(void* const* d_in, const int* in_sizes, int n_in,
                              void* d_out, int out_size)
{
    using namespace cfg;
    (void)in_sizes; (void)n_in; (void)out_size;

    const float* x     = (const float*)d_in[0];
    const float* gamma = (const float*)d_in[1];
    const float* beta  = (const float*)d_in[2];
    const float* Wq    = (const float*)d_in[3];
    const float* bq    = (const float*)d_in[4];
    const float* Wk    = (const float*)d_in[5];
    const float* bk    = (const float*)d_in[6];
    const float* Wv    = (const float*)d_in[7];
    const float* bv    = (const float*)d_in[8];
    const float* Wp    = (const float*)d_in[9];
    const float* bp    = (const float*)d_in[10];
    float* out = (float*)d_out;

    float *hnT, *qT, *kT, *v, *S0, *S1, *W;
    cudaGetSymbolAddress((void**)&hnT, g_hnT);
    cudaGetSymbolAddress((void**)&qT,  g_qT);
    cudaGetSymbolAddress((void**)&kT,  g_kT);
    cudaGetSymbolAddress((void**)&v,   g_v);
    cudaGetSymbolAddress((void**)&S0,  g_S0);
    cudaGetSymbolAddress((void**)&S1,  g_S1);
    cudaGetSymbolAddress((void**)&W,   g_W);
    float* rWq = W;
    float* rWk = W + (size_t)C * C;
    float* rWv = W + 2 * (size_t)C * C;
    float* rWp = W + 3 * (size_t)C * C;
    float* haT = hnT;

    cudaFuncSetAttribute(mma_gemm, cudaFuncAttributeMaxDynamicSharedMemorySize,
                         mg::SMEM_BYTES);

    const size_t sT = (size_t)HW * C;
    const int    WN = C * C;

    // 1) GroupNorm -> hnT (tf32)        [launch 0]
    groupnorm_t_kernel<<<BATCH * NG, 512>>>(x, gamma, beta, hnT);

    // 2) round all weights (one launch) [launch 1]
    round4_kernel<<<(WN + 255) / 256, 256>>>(Wq, Wk, Wv, Wp, W, WN);

    // 3) qT, kT = hnT·W^T + b[n]  (M=HW, N=C, K=C)   [launches 2,3]
    dim3 gT(C / 128, HW / 128, BATCH);
    mma_gemm<<<gT, mg::NTHR, mg::SMEM_BYTES>>>(hnT, nullptr, rWq, qT, nullptr,
                                               HW, C, C, sT, 0, sT,
                                               bq, 2, nullptr, 0, 1.f, 1);
    mma_gemm<<<gT, mg::NTHR, mg::SMEM_BYTES>>>(hnT, nullptr, rWk, kT, nullptr,
                                               HW, C, C, sT, 0, sT,
                                               bk, 2, nullptr, 0, 1.f, 1);

    // 4) v = Wv·hnT^T + bv[m]   (M=C, N=HW, K=C)     [launch 4]
    dim3 gV(HW / 128, C / 128, BATCH);
    mma_gemm<<<gV, mg::NTHR, mg::SMEM_BYTES>>>(rWv, nullptr, hnT, v, nullptr,
                                               C, HW, C, 0, sT, sT,
                                               bv, 1, nullptr, 0, 1.f, 1);

    // 5) attention core on batch pairs  [launch 5 = S-GEMM -> ncu target]
    dim3 gS(HW / 128, HW / 128, 2);
    dim3 gAV(C / 128, HW / 128, 2);
    for (int b = 0; b < BATCH; b += 2) {
        const float* qb = qT + (size_t)b * sT;
        const float* kb = kT + (size_t)b * sT;
        const float* vb = v  + (size_t)b * sT;
        float*       hb = haT + (size_t)b * sT;

        // S{0,1} = scale·(qT·kT^T)   (M=N=HW, K=C); z=1 -> S1 via Dalt
        mma_gemm<<<gS, mg::NTHR, mg::SMEM_BYTES>>>(qb, nullptr, kb, S0, S1,
                                                   HW, HW, C, sT, sT, 0,
                                                   nullptr, 0, nullptr, 0,
                                                   SCALE, 0);
        softmax_kernel<<<2 * HW, 256>>>(S0, S1);
        // haT = P·v^T   (M=HW, N=C, K=HW); z=1 -> S1 via Aalt
        mma_gemm<<<gAV, mg::NTHR, mg::SMEM_BYTES>>>(S0, S1, vb, hb, nullptr,
                                                    HW, C, HW, 0, sT, sT,
                                                    nullptr, 0, nullptr, 0,
                                                    1.f, 1);
    }

    // 6) out = x + Wp·haT^T + bp[m]   (M=C, N=HW, K=C)
    mma_gemm<<<gV, mg::NTHR, mg::SMEM_BYTES>>>(rWp, nullptr, haT, out, nullptr,
                                               C, HW, C, 0, sT, sT,
                                               bp, 1, x, sT, 1.f, 0);
}

// round 15
// speedup vs baseline: 1.4926x; 1.4926x over previous
#include <cuda_runtime.h>
#include <cstdint>

// ============================================================================
// AttentionBlock via mma.sync tf32 (baseline PTX target sm_103).
//   GroupNorm -> hnT (tf32, transposed)
//   qT = hnT·Wq^T, kT = hnT·Wk^T ; v = Wv·hnT^T   (tf32 out)
//   S = scale·(qT·kT^T) -> row softmax (tf32 out) -> haT = P·v^T
//   out = x + Wp·haT^T + bp
//
// R15: R13 shape (256 thr, 2x4 warps, 64x32 warp tile, 128 regs, 2 CTA/SM,
// 3-stage cp.async) + ldmatrix fragment loads: 8 LDSM replace 24 LDS.32 per
// ks-step (tf32 fragments via b16-view m8n8 ldmatrix; swizzle is 16B-granular
// so addresses stay compatible).
// Statics: all symbols <= 64 MB (container constraint).
// ============================================================================

namespace cfg {
constexpr int BATCH = 8;
constexpr int C     = 512;
constexpr int HW    = 4096;
constexpr int NG    = 32;
constexpr int CPG   = C / NG;
constexpr float EPS   = 1e-5f;
constexpr float SCALE = 0.04419417382415922f;  // 1/sqrt(512)

constexpr size_t SZ_CH = (size_t)BATCH * C * HW;   // 64 MB
constexpr size_t SZ_S1 = (size_t)HW * HW;          // 64 MB (one batch)
}

__device__ float g_hnT[cfg::SZ_CH];
__device__ float g_qT [cfg::SZ_CH];
__device__ float g_kT [cfg::SZ_CH];
__device__ float g_v  [cfg::SZ_CH];
__device__ float g_S0 [cfg::SZ_S1];
__device__ float g_S1 [cfg::SZ_S1];
__device__ float g_W  [4][cfg::C * cfg::C];

// -------------------- helpers ------------------------------------------------
__device__ __forceinline__ float tf32r(float x) {
    uint32_t u;
    asm("cvt.rna.tf32.f32 %0, %1;" : "=r"(u) : "f"(x));
    return __uint_as_float(u);
}
__device__ __forceinline__ uint32_t smem_u32(const void* p) {
    uint32_t a;
    asm("{ .reg .u64 t; cvta.to.shared.u64 t, %1; cvt.u32.u64 %0, t; }"
        : "=r"(a) : "l"(p));
    return a;
}
__device__ __forceinline__ void cp16(uint32_t dst, const void* src) {
    asm volatile("cp.async.cg.shared.global [%0], [%1], 16;"
                 :: "r"(dst), "l"(src));
}
__device__ __forceinline__ void cp_commit() {
    asm volatile("cp.async.commit_group;" ::: "memory");
}
template<int N> __device__ __forceinline__ void cp_wait() {
    asm volatile("cp.async.wait_group %0;" :: "n"(N) : "memory");
}
__device__ __forceinline__ void mma_tf32(float* d, const uint32_t* a,
                                         const uint32_t* b) {
    asm volatile(
        "mma.sync.aligned.m16n8k8.row.col.f32.tf32.tf32.f32 "
        "{%0,%1,%2,%3}, {%4,%5,%6,%7}, {%8,%9}, {%0,%1,%2,%3};"
        : "+f"(d[0]), "+f"(d[1]), "+f"(d[2]), "+f"(d[3])
        : "r"(a[0]), "r"(a[1]), "r"(a[2]), "r"(a[3]), "r"(b[0]), "r"(b[1]));
}
__device__ __forceinline__ void ldsm_x4(uint32_t* r, uint32_t addr) {
    asm volatile(
        "ldmatrix.sync.aligned.m8n8.x4.shared.b16 {%0,%1,%2,%3}, [%4];"
        : "=r"(r[0]), "=r"(r[1]), "=r"(r[2]), "=r"(r[3]) : "r"(addr));
}
__device__ __forceinline__ void ldsm_x2(uint32_t* r, uint32_t addr) {
    asm volatile(
        "ldmatrix.sync.aligned.m8n8.x2.shared.b16 {%0,%1}, [%2];"
        : "=r"(r[0]), "=r"(r[1]) : "r"(addr));
}

// -------------------- GroupNorm -> transposed tf32 output -------------------
__global__ __launch_bounds__(512)
void groupnorm_t_kernel(const float* __restrict__ x,
                        const float* __restrict__ gamma,
                        const float* __restrict__ beta,
                        float* __restrict__ outT)
{
    using namespace cfg;
    __shared__ float shs[16], shss[16];
    const int b = blockIdx.x >> 5;
    const int g = blockIdx.x & 31;
    const size_t base = ((size_t)b * C + (size_t)g * CPG) * HW;
    const int n = CPG * HW;

    float s = 0.f, ss = 0.f;
    for (int i = threadIdx.x; i < n; i += 512) {
        float v = x[base + i];
        s += v; ss += v * v;
    }
#pragma unroll
    for (int o = 16; o; o >>= 1) {
        s  += __shfl_xor_sync(0xffffffffu, s,  o);
        ss += __shfl_xor_sync(0xffffffffu, ss, o);
    }
    const int w = threadIdx.x >> 5;
    if ((threadIdx.x & 31) == 0) { shs[w] = s; shss[w] = ss; }
    __syncthreads();
    s = 0.f; ss = 0.f;
#pragma unroll
    for (int i = 0; i < 16; i++) { s += shs[i]; ss += shss[i]; }

    const float mean = s / n;
    const float var  = ss / n - mean * mean;
    const float rstd = rsqrtf(var + EPS);

    float gm[16], bt[16];
#pragma unroll
    for (int c = 0; c < 16; c++) {
        gm[c] = gamma[g * CPG + c] * rstd;
        bt[c] = beta[g * CPG + c];
    }
    for (int hw = threadIdx.x; hw < HW; hw += 512) {
        float vals[16];
#pragma unroll
        for (int c = 0; c < 16; c++)
            vals[c] = tf32r((x[base + (size_t)c * HW + hw] - mean) * gm[c] + bt[c]);
        float4* dst = reinterpret_cast<float4*>(
            outT + ((size_t)b * HW + hw) * C + g * CPG);
#pragma unroll
        for (int j = 0; j < 4; j++)
            dst[j] = make_float4(vals[4*j], vals[4*j+1], vals[4*j+2], vals[4*j+3]);
    }
}

// -------------------- round all 4 weights in one launch ----------------------
__global__ __launch_bounds__(256)
void round4_kernel(const float* __restrict__ w0, const float* __restrict__ w1,
                   const float* __restrict__ w2, const float* __restrict__ w3,
                   float* __restrict__ out, int n)
{
    int i = blockIdx.x * 256 + threadIdx.x;
    if (i < n) {
        out[i]         = tf32r(w0[i]);
        out[i + n]     = tf32r(w1[i]);
        out[i + 2 * n] = tf32r(w2[i]);
        out[i + 3 * n] = tf32r(w3[i]);
    }
}

// -------------------- Row softmax over 4096 (tf32 out), two buffers ---------
__global__ __launch_bounds__(256)
void softmax_kernel(float* __restrict__ S0, float* __restrict__ S1)
{
    using namespace cfg;
    __shared__ float shm[8], shsum[8];
    const int row = blockIdx.x;
    float* p = (row < HW) ? (S0 + (size_t)row * HW)
                          : (S1 + (size_t)(row - HW) * HW);
    const int t = threadIdx.x;

    float vals[16];
    float m = -3.4e38f;
#pragma unroll
    for (int i = 0; i < 16; i++) {
        vals[i] = p[t + i * 256];
        m = fmaxf(m, vals[i]);
    }
#pragma unroll
    for (int o = 16; o; o >>= 1) m = fmaxf(m, __shfl_xor_sync(0xffffffffu, m, o));
    if ((t & 31) == 0) shm[t >> 5] = m;
    __syncthreads();
    m = shm[0];
#pragma unroll
    for (int w = 1; w < 8; w++) m = fmaxf(m, shm[w]);

    float s = 0.f;
#pragma unroll
    for (int i = 0; i < 16; i++) {
        vals[i] = __expf(vals[i] - m);
        s += vals[i];
    }
#pragma unroll
    for (int o = 16; o; o >>= 1) s += __shfl_xor_sync(0xffffffffu, s, o);
    if ((t & 31) == 0) shsum[t >> 5] = s;
    __syncthreads();
    s = 0.f;
#pragma unroll
    for (int w = 0; w < 8; w++) s += shsum[w];

    const float inv = 1.f / s;
#pragma unroll
    for (int i = 0; i < 16; i++) p[t + i * 256] = tf32r(vals[i] * inv);
}

// ============================================================================
// Unified GEMM: 128x128x32 tile, 256 thr (8 warps 2x4), warp tile 64x32,
// ldmatrix fragment loads, 3-stage cp.async, 2 CTAs/SM.
//   D = scale*A·B^T (+bias[m]/[n]) (+resid); Aalt/Dalt replace A/D at z==1.
// ============================================================================
namespace mg {
constexpr int BM = 128, BN = 128, BK = 32;
constexpr int STAGE_BYTES = (BM + BN) * BK * 4;      // 32 KB
constexpr int NSTAGE = 3;
constexpr int SMEM_BYTES = NSTAGE * STAGE_BYTES;     // 96 KB
constexpr int NTHR = 256;
}

__global__ __launch_bounds__(256, 2)
void mma_gemm(const float* __restrict__ A, const float* __restrict__ Aalt,
              const float* __restrict__ B,
              float* __restrict__ D, float* __restrict__ Dalt,
              int M, int N, int K,
              size_t sA, size_t sB, size_t sD,
              const float* __restrict__ bias, int bias_mode,
              const float* __restrict__ resid, size_t sR,
              float scale, int round_out)
{
    using namespace mg;
    extern __shared__ char smem[];
    const uint32_t sbase = smem_u32(smem);

    const int z = blockIdx.z;
    if (Aalt && z == 1) A = Aalt; else A += (size_t)z * sA;
    B += (size_t)z * sB;
    if (Dalt && z == 1) D = Dalt; else D += (size_t)z * sD;

    const int bm = blockIdx.y * BM;
    const int bn = blockIdx.x * BN;
    const int tid = threadIdx.x;
    const int wid = tid >> 5, lid = tid & 31;
    const int wm = wid >> 2;           // 0..1 (64 rows)
    const int wn = wid & 3;            // 0..3 (32 cols)
    const int grp = lid >> 2, thr = lid & 3;
    const int NC = K / BK;

    // ---- cp.async load geometry: 4 16B-chunks per tile per thread ----
    uint32_t dstA[4], dstB[4];
    const float* srcA[4];
    const float* srcB[4];
#pragma unroll
    for (int l = 0; l < 4; l++) {
        const int c = tid + l * NTHR;      // 0..1023
        const int row = c >> 3, u = c & 7;
        const uint32_t sw = row * 128 + ((u * 16) ^ ((row & 7) << 4));
        dstA[l] = sbase + sw;
        dstB[l] = sbase + BM * BK * 4 + sw;
        srcA[l] = A + (size_t)(bm + row) * K + u * 4;
        srcB[l] = B + (size_t)(bn + row) * K + u * 4;
    }

    auto load_chunk = [&](int kc) {
        const uint32_t so = (kc % NSTAGE) * STAGE_BYTES;
        const int ko = kc * BK;
#pragma unroll
        for (int l = 0; l < 4; l++) cp16(dstA[l] + so, srcA[l] + ko);
#pragma unroll
        for (int l = 0; l < 4; l++) cp16(dstB[l] + so, srcB[l] + ko);
        cp_commit();
    };

    // ---- ldmatrix per-lane address bases ----
    // A x4: lanes 0-7 -> (rows +0, bytes +0); 8-15 -> (+8, +0);
    //       16-23 -> (+0, +16); 24-31 -> (+8, +16)
    const int aRsel = (lid >> 3) & 1;
    const int aCsel = (lid >> 4) & 1;
    const uint32_t aXor = (uint32_t)((lid & 7) << 4);
    uint32_t baseA[4];
#pragma unroll
    for (int mt = 0; mt < 4; mt++) {
        const int row = wm * 64 + mt * 16 + (lid & 7) + aRsel * 8;
        baseA[mt] = sbase + row * 128;
    }
    // B x2: lanes 0-7 -> bytes +0; 8-15 -> bytes +16 (lanes 16-31 mirror 0-15)
    const int lb = lid & 15;
    const int bCsel = lb >> 3;
    const uint32_t bXor = (uint32_t)((lb & 7) << 4);
    uint32_t baseB[4];
#pragma unroll
    for (int nt = 0; nt < 4; nt++) {
        const int row = wn * 32 + nt * 8 + (lb & 7);
        baseB[nt] = sbase + BM * BK * 4 + row * 128;
    }

    float acc[4][4][4];
#pragma unroll
    for (int i = 0; i < 4; i++)
#pragma unroll
        for (int j = 0; j < 4; j++)
#pragma unroll
            for (int r = 0; r < 4; r++) acc[i][j][r] = 0.f;

    load_chunk(0);
    load_chunk(1);

    for (int kc = 0; kc < NC; kc++) {
        if (kc < NC - 1) cp_wait<1>(); else cp_wait<0>();
        __syncthreads();
        if (kc + 2 < NC) load_chunk(kc + 2);

        const uint32_t stoff = (uint32_t)((kc % NSTAGE) * STAGE_BYTES);

#pragma unroll
        for (int ks = 0; ks < BK / 8; ks++) {
            const uint32_t offA = stoff + (((uint32_t)(ks * 32 + aCsel * 16)) ^ aXor);
            const uint32_t offB = stoff + (((uint32_t)(ks * 32 + bCsel * 16)) ^ bXor);

            uint32_t a[4][4];
#pragma unroll
            for (int mt = 0; mt < 4; mt++) ldsm_x4(a[mt], baseA[mt] + offA);
            uint32_t b[4][2];
#pragma unroll
            for (int nt = 0; nt < 4; nt++) ldsm_x2(b[nt], baseB[nt] + offB);

#pragma unroll
            for (int mt = 0; mt < 4; mt++)
#pragma unroll
                for (int nt = 0; nt < 4; nt++)
                    mma_tf32(acc[mt][nt], a[mt], b[nt]);
        }
    }

    // ---- epilogue ----
#pragma unroll
    for (int mt = 0; mt < 4; mt++) {
#pragma unroll
        for (int half = 0; half < 2; half++) {
            const int m = bm + wm * 64 + mt * 16 + grp + half * 8;
            const float biasM = (bias_mode == 1) ? bias[m] : 0.f;
#pragma unroll
            for (int nt = 0; nt < 4; nt++) {
                const int n = bn + wn * 32 + nt * 8 + 2 * thr;
                float v0 = acc[mt][nt][half * 2 + 0] * scale;
                float v1 = acc[mt][nt][half * 2 + 1] * scale;
                if (bias_mode == 1) { v0 += biasM; v1 += biasM; }
                else if (bias_mode == 2) { v0 += bias[n]; v1 += bias[n + 1]; }
                const size_t off = (size_t)m * N + n;
                if (resid) {
                    const float* rp = resid + (size_t)z * sR;
                    v0 += rp[off]; v1 += rp[off + 1];
                }
                if (round_out) { v0 = tf32r(v0); v1 = tf32r(v1); }
                *reinterpret_cast<float2*>(D + off) = make_float2(v0, v1);
            }
        }
    }
}

// -------------------- launch ------------------------------------------------
extern "C" void kernel_launch(void* const* d_in, const int* in_sizes, int n_in,
                              void* d_out, int out_size)
{
    using namespace cfg;
    (void)in_sizes; (void)n_in; (void)out_size;

    const float* x     = (const float*)d_in[0];
    const float* gamma = (const float*)d_in[1];
    const float* beta  = (const float*)d_in[2];
    const float* Wq    = (const float*)d_in[3];
    const float* bq    = (const float*)d_in[4];
    const float* Wk    = (const float*)d_in[5];
    const float* bk    = (const float*)d_in[6];
    const float* Wv    = (const float*)d_in[7];
    const float* bv    = (const float*)d_in[8];
    const float* Wp    = (const float*)d_in[9];
    const float* bp    = (const float*)d_in[10];
    float* out = (float*)d_out;

    float *hnT, *qT, *kT, *v, *S0, *S1, *W;
    cudaGetSymbolAddress((void**)&hnT, g_hnT);
    cudaGetSymbolAddress((void**)&qT,  g_qT);
    cudaGetSymbolAddress((void**)&kT,  g_kT);
    cudaGetSymbolAddress((void**)&v,   g_v);
    cudaGetSymbolAddress((void**)&S0,  g_S0);
    cudaGetSymbolAddress((void**)&S1,  g_S1);
    cudaGetSymbolAddress((void**)&W,   g_W);
    float* rWq = W;
    float* rWk = W + (size_t)C * C;
    float* rWv = W + 2 * (size_t)C * C;
    float* rWp = W + 3 * (size_t)C * C;
    float* haT = hnT;

    cudaFuncSetAttribute(mma_gemm, cudaFuncAttributeMaxDynamicSharedMemorySize,
                         mg::SMEM_BYTES);

    const size_t sT = (size_t)HW * C;
    const int    WN = C * C;

    // 1) GroupNorm -> hnT (tf32)        [launch 0]
    groupnorm_t_kernel<<<BATCH * NG, 512>>>(x, gamma, beta, hnT);

    // 2) round all weights (one launch) [launch 1]
    round4_kernel<<<(WN + 255) / 256, 256>>>(Wq, Wk, Wv, Wp, W, WN);

    // 3) qT, kT = hnT·W^T + b[n]  (M=HW, N=C, K=C)   [launches 2,3]
    dim3 gT(C / 128, HW / 128, BATCH);
    mma_gemm<<<gT, mg::NTHR, mg::SMEM_BYTES>>>(hnT, nullptr, rWq, qT, nullptr,
                                               HW, C, C, sT, 0, sT,
                                               bq, 2, nullptr, 0, 1.f, 1);
    mma_gemm<<<gT, mg::NTHR, mg::SMEM_BYTES>>>(hnT, nullptr, rWk, kT, nullptr,
                                               HW, C, C, sT, 0, sT,
                                               bk, 2, nullptr, 0, 1.f, 1);

    // 4) v = Wv·hnT^T + bv[m]   (M=C, N=HW, K=C)     [launch 4]
    dim3 gV(HW / 128, C / 128, BATCH);
    mma_gemm<<<gV, mg::NTHR, mg::SMEM_BYTES>>>(rWv, nullptr, hnT, v, nullptr,
                                               C, HW, C, 0, sT, sT,
                                               bv, 1, nullptr, 0, 1.f, 1);

    // 5) attention core on batch pairs  [launch 5 = S-GEMM -> ncu target]
    dim3 gS(HW / 128, HW / 128, 2);
    dim3 gAV(C / 128, HW / 128, 2);
    for (int b = 0; b < BATCH; b += 2) {
        const float* qb = qT + (size_t)b * sT;
        const float* kb = kT + (size_t)b * sT;
        const float* vb = v  + (size_t)b * sT;
        float*       hb = haT + (size_t)b * sT;

        // S{0,1} = scale·(qT·kT^T)   (M=N=HW, K=C); z=1 -> S1 via Dalt
        mma_gemm<<<gS, mg::NTHR, mg::SMEM_BYTES>>>(qb, nullptr, kb, S0, S1,
                                                   HW, HW, C, sT, sT, 0,
                                                   nullptr, 0, nullptr, 0,
                                                   SCALE, 0);
        softmax_kernel<<<2 * HW, 256>>>(S0, S1);
        // haT = P·v^T   (M=HW, N=C, K=HW); z=1 -> S1 via Aalt
        mma_gemm<<<gAV, mg::NTHR, mg::SMEM_BYTES>>>(S0, S1, vb, hb, nullptr,
                                                    HW, C, HW, 0, sT, sT,
                                                    nullptr, 0, nullptr, 0,
                                                    1.f, 1);
    }

    // 6) out = x + Wp·haT^T + bp[m]   (M=C, N=HW, K=C)
    mma_gemm<<<gV, mg::NTHR, mg::SMEM_BYTES>>>(rWp, nullptr, haT, out, nullptr,
                                               C, HW, C, 0, sT, sT,
                                               bp, 1, x, sT, 1.f, 0);
}

// round 17
// speedup vs baseline: 1.5152x; 1.0152x over previous
#include <cuda_runtime.h>
#include <cstdint>

// ============================================================================
// AttentionBlock via mma.sync tf32 (baseline PTX target sm_103).
//   GroupNorm -> hnT (tf32, transposed)
//   qT = hnT·Wq^T, kT = hnT·Wk^T ; v = Wv·hnT^T   (tf32 out)
//   S = scale·(qT·kT^T) -> row softmax (tf32 out) -> haT = P·v^T
//   out = x + Wp·haT^T + bp
//
// R17 (= R16 resubmit; R16 died to an infra flake — statics identical to the
// passing R15): B fragments loaded in nt-PAIRS via ldmatrix.x4 (6 LDSM per
// ks-step instead of 8; LDSM floor 4cyc -> 24cyc < 16 MMA ~32cyc, so the
// tensor pipe becomes the sole steady-state critical path).
// Statics: all symbols <= 64 MB (container constraint).
// ============================================================================

namespace cfg {
constexpr int BATCH = 8;
constexpr int C     = 512;
constexpr int HW    = 4096;
constexpr int NG    = 32;
constexpr int CPG   = C / NG;
constexpr float EPS   = 1e-5f;
constexpr float SCALE = 0.04419417382415922f;  // 1/sqrt(512)

constexpr size_t SZ_CH = (size_t)BATCH * C * HW;   // 64 MB
constexpr size_t SZ_S1 = (size_t)HW * HW;          // 64 MB (one batch)
}

__device__ float g_hnT[cfg::SZ_CH];
__device__ float g_qT [cfg::SZ_CH];
__device__ float g_kT [cfg::SZ_CH];
__device__ float g_v  [cfg::SZ_CH];
__device__ float g_S0 [cfg::SZ_S1];
__device__ float g_S1 [cfg::SZ_S1];
__device__ float g_W  [4][cfg::C * cfg::C];

// -------------------- helpers ------------------------------------------------
__device__ __forceinline__ float tf32r(float x) {
    uint32_t u;
    asm("cvt.rna.tf32.f32 %0, %1;" : "=r"(u) : "f"(x));
    return __uint_as_float(u);
}
__device__ __forceinline__ uint32_t smem_u32(const void* p) {
    uint32_t a;
    asm("{ .reg .u64 t; cvta.to.shared.u64 t, %1; cvt.u32.u64 %0, t; }"
        : "=r"(a) : "l"(p));
    return a;
}
__device__ __forceinline__ void cp16(uint32_t dst, const void* src) {
    asm volatile("cp.async.cg.shared.global [%0], [%1], 16;"
                 :: "r"(dst), "l"(src));
}
__device__ __forceinline__ void cp_commit() {
    asm volatile("cp.async.commit_group;" ::: "memory");
}
template<int N> __device__ __forceinline__ void cp_wait() {
    asm volatile("cp.async.wait_group %0;" :: "n"(N) : "memory");
}
__device__ __forceinline__ void mma_tf32(float* d, const uint32_t* a,
                                         const uint32_t* b) {
    asm volatile(
        "mma.sync.aligned.m16n8k8.row.col.f32.tf32.tf32.f32 "
        "{%0,%1,%2,%3}, {%4,%5,%6,%7}, {%8,%9}, {%0,%1,%2,%3};"
        : "+f"(d[0]), "+f"(d[1]), "+f"(d[2]), "+f"(d[3])
        : "r"(a[0]), "r"(a[1]), "r"(a[2]), "r"(a[3]), "r"(b[0]), "r"(b[1]));
}
__device__ __forceinline__ void ldsm_x4(uint32_t* r, uint32_t addr) {
    asm volatile(
        "ldmatrix.sync.aligned.m8n8.x4.shared.b16 {%0,%1,%2,%3}, [%4];"
        : "=r"(r[0]), "=r"(r[1]), "=r"(r[2]), "=r"(r[3]) : "r"(addr));
}

// -------------------- GroupNorm -> transposed tf32 output -------------------
__global__ __launch_bounds__(512)
void groupnorm_t_kernel(const float* __restrict__ x,
                        const float* __restrict__ gamma,
                        const float* __restrict__ beta,
                        float* __restrict__ outT)
{
    using namespace cfg;
    __shared__ float shs[16], shss[16];
    const int b = blockIdx.x >> 5;
    const int g = blockIdx.x & 31;
    const size_t base = ((size_t)b * C + (size_t)g * CPG) * HW;
    const int n = CPG * HW;

    float s = 0.f, ss = 0.f;
    for (int i = threadIdx.x; i < n; i += 512) {
        float v = x[base + i];
        s += v; ss += v * v;
    }
#pragma unroll
    for (int o = 16; o; o >>= 1) {
        s  += __shfl_xor_sync(0xffffffffu, s,  o);
        ss += __shfl_xor_sync(0xffffffffu, ss, o);
    }
    const int w = threadIdx.x >> 5;
    if ((threadIdx.x & 31) == 0) { shs[w] = s; shss[w] = ss; }
    __syncthreads();
    s = 0.f; ss = 0.f;
#pragma unroll
    for (int i = 0; i < 16; i++) { s += shs[i]; ss += shss[i]; }

    const float mean = s / n;
    const float var  = ss / n - mean * mean;
    const float rstd = rsqrtf(var + EPS);

    float gm[16], bt[16];
#pragma unroll
    for (int c = 0; c < 16; c++) {
        gm[c] = gamma[g * CPG + c] * rstd;
        bt[c] = beta[g * CPG + c];
    }
    for (int hw = threadIdx.x; hw < HW; hw += 512) {
        float vals[16];
#pragma unroll
        for (int c = 0; c < 16; c++)
            vals[c] = tf32r((x[base + (size_t)c * HW + hw] - mean) * gm[c] + bt[c]);
        float4* dst = reinterpret_cast<float4*>(
            outT + ((size_t)b * HW + hw) * C + g * CPG);
#pragma unroll
        for (int j = 0; j < 4; j++)
            dst[j] = make_float4(vals[4*j], vals[4*j+1], vals[4*j+2], vals[4*j+3]);
    }
}

// -------------------- round all 4 weights in one launch ----------------------
__global__ __launch_bounds__(256)
void round4_kernel(const float* __restrict__ w0, const float* __restrict__ w1,
                   const float* __restrict__ w2, const float* __restrict__ w3,
                   float* __restrict__ out, int n)
{
    int i = blockIdx.x * 256 + threadIdx.x;
    if (i < n) {
        out[i]         = tf32r(w0[i]);
        out[i + n]     = tf32r(w1[i]);
        out[i + 2 * n] = tf32r(w2[i]);
        out[i + 3 * n] = tf32r(w3[i]);
    }
}

// -------------------- Row softmax over 4096 (tf32 out), two buffers ---------
__global__ __launch_bounds__(256)
void softmax_kernel(float* __restrict__ S0, float* __restrict__ S1)
{
    using namespace cfg;
    __shared__ float shm[8], shsum[8];
    const int row = blockIdx.x;
    float* p = (row < HW) ? (S0 + (size_t)row * HW)
                          : (S1 + (size_t)(row - HW) * HW);
    const int t = threadIdx.x;

    float vals[16];
    float m = -3.4e38f;
#pragma unroll
    for (int i = 0; i < 16; i++) {
        vals[i] = p[t + i * 256];
        m = fmaxf(m, vals[i]);
    }
#pragma unroll
    for (int o = 16; o; o >>= 1) m = fmaxf(m, __shfl_xor_sync(0xffffffffu, m, o));
    if ((t & 31) == 0) shm[t >> 5] = m;
    __syncthreads();
    m = shm[0];
#pragma unroll
    for (int w = 1; w < 8; w++) m = fmaxf(m, shm[w]);

    float s = 0.f;
#pragma unroll
    for (int i = 0; i < 16; i++) {
        vals[i] = __expf(vals[i] - m);
        s += vals[i];
    }
#pragma unroll
    for (int o = 16; o; o >>= 1) s += __shfl_xor_sync(0xffffffffu, s, o);
    if ((t & 31) == 0) shsum[t >> 5] = s;
    __syncthreads();
    s = 0.f;
#pragma unroll
    for (int w = 0; w < 8; w++) s += shsum[w];

    const float inv = 1.f / s;
#pragma unroll
    for (int i = 0; i < 16; i++) p[t + i * 256] = tf32r(vals[i] * inv);
}

// ============================================================================
// Unified GEMM: 128x128x32 tile, 256 thr (8 warps 2x4), warp tile 64x32,
// ldmatrix fragment loads (A: 4x x4; B: 2x x4 covering nt-pairs),
// 3-stage cp.async, 2 CTAs/SM.
//   D = scale*A·B^T (+bias[m]/[n]) (+resid); Aalt/Dalt replace A/D at z==1.
// ============================================================================
namespace mg {
constexpr int BM = 128, BN = 128, BK = 32;
constexpr int STAGE_BYTES = (BM + BN) * BK * 4;      // 32 KB
constexpr int NSTAGE = 3;
constexpr int SMEM_BYTES = NSTAGE * STAGE_BYTES;     // 96 KB
constexpr int NTHR = 256;
}

__global__ __launch_bounds__(256, 2)
void mma_gemm(const float* __restrict__ A, const float* __restrict__ Aalt,
              const float* __restrict__ B,
              float* __restrict__ D, float* __restrict__ Dalt,
              int M, int N, int K,
              size_t sA, size_t sB, size_t sD,
              const float* __restrict__ bias, int bias_mode,
              const float* __restrict__ resid, size_t sR,
              float scale, int round_out)
{
    using namespace mg;
    extern __shared__ char smem[];
    const uint32_t sbase = smem_u32(smem);

    const int z = blockIdx.z;
    if (Aalt && z == 1) A = Aalt; else A += (size_t)z * sA;
    B += (size_t)z * sB;
    if (Dalt && z == 1) D = Dalt; else D += (size_t)z * sD;

    const int bm = blockIdx.y * BM;
    const int bn = blockIdx.x * BN;
    const int tid = threadIdx.x;
    const int wid = tid >> 5, lid = tid & 31;
    const int wm = wid >> 2;           // 0..1 (64 rows)
    const int wn = wid & 3;            // 0..3 (32 cols)
    const int grp = lid >> 2, thr = lid & 3;
    const int NC = K / BK;

    // ---- cp.async load geometry: 4 16B-chunks per tile per thread ----
    uint32_t dstA[4], dstB[4];
    const float* srcA[4];
    const float* srcB[4];
#pragma unroll
    for (int l = 0; l < 4; l++) {
        const int c = tid + l * NTHR;      // 0..1023
        const int row = c >> 3, u = c & 7;
        const uint32_t sw = row * 128 + ((u * 16) ^ ((row & 7) << 4));
        dstA[l] = sbase + sw;
        dstB[l] = sbase + BM * BK * 4 + sw;
        srcA[l] = A + (size_t)(bm + row) * K + u * 4;
        srcB[l] = B + (size_t)(bn + row) * K + u * 4;
    }

    auto load_chunk = [&](int kc) {
        const uint32_t so = (kc % NSTAGE) * STAGE_BYTES;
        const int ko = kc * BK;
#pragma unroll
        for (int l = 0; l < 4; l++) cp16(dstA[l] + so, srcA[l] + ko);
#pragma unroll
        for (int l = 0; l < 4; l++) cp16(dstB[l] + so, srcB[l] + ko);
        cp_commit();
    };

    // ---- ldmatrix per-lane address bases ----
    // A x4 (one mt = 16 rows x both k-halves):
    //   lanes 0-7 -> (row +0, khalf0); 8-15 -> (+8, khalf0);
    //   16-23 -> (+0, khalf1); 24-31 -> (+8, khalf1)
    const int aRsel = (lid >> 3) & 1;
    const int aCsel = (lid >> 4) & 1;
    const uint32_t lXor = (uint32_t)((lid & 7) << 4);
    uint32_t baseA[4];
#pragma unroll
    for (int mt = 0; mt < 4; mt++) {
        const int row = wm * 64 + mt * 16 + (lid & 7) + aRsel * 8;
        baseA[mt] = sbase + row * 128;
    }
    // B x4 (one nt-PAIR = 16 N-rows x both k-halves):
    //   lanes 0-7  -> (nt,   khalf0) ; 8-15  -> (nt,   khalf1)
    //   lanes 16-23-> (nt+1, khalf0) ; 24-31 -> (nt+1, khalf1)
    //   => r0,r1 = b[nt]; r2,r3 = b[nt+1]
    const int bRsel = (lid >> 4) & 1;
    const int bCsel = (lid >> 3) & 1;
    uint32_t baseB[2];
#pragma unroll
    for (int p = 0; p < 2; p++) {
        const int row = wn * 32 + p * 16 + bRsel * 8 + (lid & 7);
        baseB[p] = sbase + BM * BK * 4 + row * 128;
    }

    float acc[4][4][4];
#pragma unroll
    for (int i = 0; i < 4; i++)
#pragma unroll
        for (int j = 0; j < 4; j++)
#pragma unroll
            for (int r = 0; r < 4; r++) acc[i][j][r] = 0.f;

    load_chunk(0);
    load_chunk(1);

    for (int kc = 0; kc < NC; kc++) {
        if (kc < NC - 1) cp_wait<1>(); else cp_wait<0>();
        __syncthreads();
        if (kc + 2 < NC) load_chunk(kc + 2);

        const uint32_t stoff = (uint32_t)((kc % NSTAGE) * STAGE_BYTES);

#pragma unroll
        for (int ks = 0; ks < BK / 8; ks++) {
            const uint32_t offA = stoff + (((uint32_t)(ks * 32 + aCsel * 16)) ^ lXor);
            const uint32_t offB = stoff + (((uint32_t)(ks * 32 + bCsel * 16)) ^ lXor);

            uint32_t a[4][4];
#pragma unroll
            for (int mt = 0; mt < 4; mt++) ldsm_x4(a[mt], baseA[mt] + offA);
            uint32_t b[2][4];   // [pair][r0..r3] = {b[2p], b[2p+1]}
#pragma unroll
            for (int p = 0; p < 2; p++) ldsm_x4(b[p], baseB[p] + offB);

#pragma unroll
            for (int mt = 0; mt < 4; mt++)
#pragma unroll
                for (int nt = 0; nt < 4; nt++)
                    mma_tf32(acc[mt][nt], a[mt], &b[nt >> 1][(nt & 1) * 2]);
        }
    }

    // ---- epilogue ----
#pragma unroll
    for (int mt = 0; mt < 4; mt++) {
#pragma unroll
        for (int half = 0; half < 2; half++) {
            const int m = bm + wm * 64 + mt * 16 + grp + half * 8;
            const float biasM = (bias_mode == 1) ? bias[m] : 0.f;
#pragma unroll
            for (int nt = 0; nt < 4; nt++) {
                const int n = bn + wn * 32 + nt * 8 + 2 * thr;
                float v0 = acc[mt][nt][half * 2 + 0] * scale;
                float v1 = acc[mt][nt][half * 2 + 1] * scale;
                if (bias_mode == 1) { v0 += biasM; v1 += biasM; }
                else if (bias_mode == 2) { v0 += bias[n]; v1 += bias[n + 1]; }
                const size_t off = (size_t)m * N + n;
                if (resid) {
                    const float* rp = resid + (size_t)z * sR;
                    v0 += rp[off]; v1 += rp[off + 1];
                }
                if (round_out) { v0 = tf32r(v0); v1 = tf32r(v1); }
                *reinterpret_cast<float2*>(D + off) = make_float2(v0, v1);
            }
        }
    }
}

// -------------------- launch ------------------------------------------------
extern "C" void kernel_launch(void* const* d_in, const int* in_sizes, int n_in,
                              void* d_out, int out_size)
{
    using namespace cfg;
    (void)in_sizes; (void)n_in; (void)out_size;

    const float* x     = (const float*)d_in[0];
    const float* gamma = (const float*)d_in[1];
    const float* beta  = (const float*)d_in[2];
    const float* Wq    = (const float*)d_in[3];
    const float* bq    = (const float*)d_in[4];
    const float* Wk    = (const float*)d_in[5];
    const float* bk    = (const float*)d_in[6];
    const float* Wv    = (const float*)d_in[7];
    const float* bv    = (const float*)d_in[8];
    const float* Wp    = (const float*)d_in[9];
    const float* bp    = (const float*)d_in[10];
    float* out = (float*)d_out;

    float *hnT, *qT, *kT, *v, *S0, *S1, *W;
    cudaGetSymbolAddress((void**)&hnT, g_hnT);
    cudaGetSymbolAddress((void**)&qT,  g_qT);
    cudaGetSymbolAddress((void**)&kT,  g_kT);
    cudaGetSymbolAddress((void**)&v,   g_v);
    cudaGetSymbolAddress((void**)&S0,  g_S0);
    cudaGetSymbolAddress((void**)&S1,  g_S1);
    cudaGetSymbolAddress((void**)&W,   g_W);
    float* rWq = W;
    float* rWk = W + (size_t)C * C;
    float* rWv = W + 2 * (size_t)C * C;
    float* rWp = W + 3 * (size_t)C * C;
    float* haT = hnT;

    cudaFuncSetAttribute(mma_gemm, cudaFuncAttributeMaxDynamicSharedMemorySize,
                         mg::SMEM_BYTES);

    const size_t sT = (size_t)HW * C;
    const int    WN = C * C;

    // 1) GroupNorm -> hnT (tf32)        [launch 0]
    groupnorm_t_kernel<<<BATCH * NG, 512>>>(x, gamma, beta, hnT);

    // 2) round all weights (one launch) [launch 1]
    round4_kernel<<<(WN + 255) / 256, 256>>>(Wq, Wk, Wv, Wp, W, WN);

    // 3) qT, kT = hnT·W^T + b[n]  (M=HW, N=C, K=C)   [launches 2,3]
    dim3 gT(C / 128, HW / 128, BATCH);
    mma_gemm<<<gT, mg::NTHR, mg::SMEM_BYTES>>>(hnT, nullptr, rWq, qT, nullptr,
                                               HW, C, C, sT, 0, sT,
                                               bq, 2, nullptr, 0, 1.f, 1);
    mma_gemm<<<gT, mg::NTHR, mg::SMEM_BYTES>>>(hnT, nullptr, rWk, kT, nullptr,
                                               HW, C, C, sT, 0, sT,
                                               bk, 2, nullptr, 0, 1.f, 1);

    // 4) v = Wv·hnT^T + bv[m]   (M=C, N=HW, K=C)     [launch 4]
    dim3 gV(HW / 128, C / 128, BATCH);
    mma_gemm<<<gV, mg::NTHR, mg::SMEM_BYTES>>>(rWv, nullptr, hnT, v, nullptr,
                                               C, HW, C, 0, sT, sT,
                                               bv, 1, nullptr, 0, 1.f, 1);

    // 5) attention core on batch pairs  [launch 5 = S-GEMM -> ncu target]
    dim3 gS(HW / 128, HW / 128, 2);
    dim3 gAV(C / 128, HW / 128, 2);
    for (int b = 0; b < BATCH; b += 2) {
        const float* qb = qT + (size_t)b * sT;
        const float* kb = kT + (size_t)b * sT;
        const float* vb = v  + (size_t)b * sT;
        float*       hb = haT + (size_t)b * sT;

        // S{0,1} = scale·(qT·kT^T)   (M=N=HW, K=C); z=1 -> S1 via Dalt
        mma_gemm<<<gS, mg::NTHR, mg::SMEM_BYTES>>>(qb, nullptr, kb, S0, S1,
                                                   HW, HW, C, sT, sT, 0,
                                                   nullptr, 0, nullptr, 0,
                                                   SCALE, 0);
        softmax_kernel<<<2 * HW, 256>>>(S0, S1);
        // haT = P·v^T   (M=HW, N=C, K=HW); z=1 -> S1 via Aalt
        mma_gemm<<<gAV, mg::NTHR, mg::SMEM_BYTES>>>(S0, S1, vb, hb, nullptr,
                                                    HW, C, HW, 0, sT, sT,
                                                    nullptr, 0, nullptr, 0,
                                                    1.f, 1);
    }

    // 6) out = x + Wp·haT^T + bp[m]   (M=C, N=HW, K=C)
    mma_gemm<<<gV, mg::NTHR, mg::SMEM_BYTES>>>(rWp, nullptr, haT, out, nullptr,
                                               C, HW, C, 0, sT, sT,
                                               bp, 1, x, sT, 1.f, 0);
}